// round 1
// baseline (speedup 1.0000x reference)
#include <cuda_runtime.h>
#include <cuda_bf16.h>

// Problem: B=4096, D=128, H=512
//   z = y @ W1 + t*v1 + b1        (B x H)
//   h = tanh(z)
//   dy = h @ W2 + b2              (B x D)
//   div[b] = sum_k (1 - h[b,k]^2) * c_k,  c_k = sum_i W1[i,k]*W2[k,i]
// Output: dy (B*D floats) followed by -div (B floats).

#define B_ 4096
#define D_ 128
#define H_ 512
#define BM 32            // rows per block
#define PAD 132          // padded row stride for smem tiles

__device__ float g_c[H_];    // c_k
__device__ float g_tb[H_];   // t*v1 + b1

__global__ void prep_kernel(const float* __restrict__ t,
                            const float* __restrict__ W1,
                            const float* __restrict__ b1,
                            const float* __restrict__ v1,
                            const float* __restrict__ W2) {
    int k = blockIdx.x * blockDim.x + threadIdx.x;
    if (k < H_) {
        float s = 0.f;
        #pragma unroll 8
        for (int i = 0; i < D_; i++) {
            s += W1[i * H_ + k] * W2[k * D_ + i];
        }
        g_c[k]  = s;
        g_tb[k] = b1[k] + t[0] * v1[k];
    }
}

__global__ __launch_bounds__(256) void ode_kernel(
    const float* __restrict__ y,
    const float* __restrict__ W1,
    const float* __restrict__ W2,
    const float* __restrict__ b2,
    float* __restrict__ out)
{
    __shared__ float sy[BM][PAD];   // y tile
    __shared__ float sh[BM][PAD];   // h chunk (BM x 128)

    const int tid  = threadIdx.x;
    const int wrp  = tid >> 5;      // 0..7  -> row group
    const int lane = tid & 31;      // 0..31 -> col group
    const int r0   = wrp * 4;
    const int c0   = lane * 4;
    const int mb   = blockIdx.x * BM;

    // Load y tile (BM x 128), coalesced float4
    for (int idx = tid; idx < BM * (D_ / 4); idx += 256) {
        int r  = idx >> 5;
        int c4 = (idx & 31) * 4;
        float4 v = *(const float4*)(y + (mb + r) * D_ + c4);
        sy[r][c4]     = v.x;
        sy[r][c4 + 1] = v.y;
        sy[r][c4 + 2] = v.z;
        sy[r][c4 + 3] = v.w;
    }
    __syncthreads();

    float acc[4][4] = {};
    float dv[4]     = {0.f, 0.f, 0.f, 0.f};

    for (int ch = 0; ch < H_ / 128; ch++) {
        // ---- Phase A: z = y_tile @ W1[:, ch*128 : ch*128+128] ----
        float z[4][4] = {};
        const float* W1c = W1 + ch * 128 + c0;
        #pragma unroll 8
        for (int i = 0; i < D_; i++) {
            float4 wv = *(const float4*)(W1c + i * H_);
            float a0 = sy[r0][i];
            float a1 = sy[r0 + 1][i];
            float a2 = sy[r0 + 2][i];
            float a3 = sy[r0 + 3][i];
            z[0][0] += a0 * wv.x; z[0][1] += a0 * wv.y; z[0][2] += a0 * wv.z; z[0][3] += a0 * wv.w;
            z[1][0] += a1 * wv.x; z[1][1] += a1 * wv.y; z[1][2] += a1 * wv.z; z[1][3] += a1 * wv.w;
            z[2][0] += a2 * wv.x; z[2][1] += a2 * wv.y; z[2][2] += a2 * wv.z; z[2][3] += a2 * wv.w;
            z[3][0] += a3 * wv.x; z[3][1] += a3 * wv.y; z[3][2] += a3 * wv.z; z[3][3] += a3 * wv.w;
        }

        const int kg = ch * 128 + c0;
        const float4 tb4 = *(const float4*)(g_tb + kg);
        const float4 cc4 = *(const float4*)(g_c + kg);
        #pragma unroll
        for (int rr = 0; rr < 4; rr++) {
            float h0 = tanhf(z[rr][0] + tb4.x);
            float h1 = tanhf(z[rr][1] + tb4.y);
            float h2 = tanhf(z[rr][2] + tb4.z);
            float h3 = tanhf(z[rr][3] + tb4.w);
            dv[rr] += cc4.x * (1.f - h0 * h0)
                    + cc4.y * (1.f - h1 * h1)
                    + cc4.z * (1.f - h2 * h2)
                    + cc4.w * (1.f - h3 * h3);
            float4 hv = make_float4(h0, h1, h2, h3);
            *(float4*)(&sh[r0 + rr][c0]) = hv;
        }
        __syncthreads();

        // ---- Phase B: acc += h_chunk @ W2[ch*128 : ch*128+128, :] ----
        const float* W2c = W2 + ch * 128 * D_ + c0;
        #pragma unroll 8
        for (int kk = 0; kk < 128; kk++) {
            float4 wv = *(const float4*)(W2c + kk * D_);
            float h0 = sh[r0][kk];
            float h1 = sh[r0 + 1][kk];
            float h2 = sh[r0 + 2][kk];
            float h3 = sh[r0 + 3][kk];
            acc[0][0] += h0 * wv.x; acc[0][1] += h0 * wv.y; acc[0][2] += h0 * wv.z; acc[0][3] += h0 * wv.w;
            acc[1][0] += h1 * wv.x; acc[1][1] += h1 * wv.y; acc[1][2] += h1 * wv.z; acc[1][3] += h1 * wv.w;
            acc[2][0] += h2 * wv.x; acc[2][1] += h2 * wv.y; acc[2][2] += h2 * wv.z; acc[2][3] += h2 * wv.w;
            acc[3][0] += h3 * wv.x; acc[3][1] += h3 * wv.y; acc[3][2] += h3 * wv.z; acc[3][3] += h3 * wv.w;
        }
        __syncthreads();
    }

    // ---- Epilogue: dy = acc + b2 ----
    const float4 b24 = *(const float4*)(b2 + c0);
    #pragma unroll
    for (int rr = 0; rr < 4; rr++) {
        float4 o;
        o.x = acc[rr][0] + b24.x;
        o.y = acc[rr][1] + b24.y;
        o.z = acc[rr][2] + b24.z;
        o.w = acc[rr][3] + b24.w;
        *(float4*)(out + (size_t)(mb + r0 + rr) * D_ + c0) = o;
    }

    // ---- Divergence: warp-reduce dv over the 32 col-groups ----
    #pragma unroll
    for (int rr = 0; rr < 4; rr++) {
        float v = dv[rr];
        #pragma unroll
        for (int off = 16; off > 0; off >>= 1)
            v += __shfl_xor_sync(0xFFFFFFFFu, v, off);
        if (lane == 0)
            out[(size_t)B_ * D_ + mb + r0 + rr] = -v;
    }
}

extern "C" void kernel_launch(void* const* d_in, const int* in_sizes, int n_in,
                              void* d_out, int out_size) {
    // Input order: t, y, logp, W1, b1, v1, W2, b2
    const float* t  = (const float*)d_in[0];
    const float* y  = (const float*)d_in[1];
    const float* W1 = (const float*)d_in[3];
    const float* b1 = (const float*)d_in[4];
    const float* v1 = (const float*)d_in[5];
    const float* W2 = (const float*)d_in[6];
    const float* b2 = (const float*)d_in[7];
    float* out = (float*)d_out;

    prep_kernel<<<1, H_>>>(t, W1, b1, v1, W2);
    ode_kernel<<<B_ / BM, 256>>>(y, W1, W2, b2, out);
}

// round 2
// speedup vs baseline: 1.2810x; 1.2810x over previous
#include <cuda_runtime.h>
#include <cuda_bf16.h>

// Problem: B=4096, D=128, H=512
//   z = y @ W1 + t*v1 + b1        (B x H)
//   h = tanh(z)
//   dy = h @ W2 + b2              (B x D)
//   div[b] = sum_k (1 - h[b,k]^2) * c_k,  c_k = sum_i W1[i,k]*W2[k,i]
// Output: dy (B*D floats) followed by -div (B floats).

#define B_ 4096
#define D_ 128
#define H_ 512
#define BM 16            // rows per block (grid = 256)
#define PAD 132          // padded row stride for smem tiles

__device__ float g_c[H_];    // c_k
__device__ float g_tb[H_];   // t*v1 + b1

__global__ void prep_kernel(const float* __restrict__ t,
                            const float* __restrict__ W1,
                            const float* __restrict__ b1,
                            const float* __restrict__ v1,
                            const float* __restrict__ W2) {
    int k = blockIdx.x * blockDim.x + threadIdx.x;
    if (k < H_) {
        float s = 0.f;
        #pragma unroll 8
        for (int i = 0; i < D_; i++) {
            s += W1[i * H_ + k] * W2[k * D_ + i];
        }
        g_c[k]  = s;
        g_tb[k] = b1[k] + t[0] * v1[k];
    }
}

__global__ __launch_bounds__(256, 2) void ode_kernel(
    const float* __restrict__ y,
    const float* __restrict__ W1,
    const float* __restrict__ W2,
    const float* __restrict__ b2,
    float* __restrict__ out)
{
    __shared__ float sy[BM][PAD];   // y tile
    __shared__ float sh[BM][PAD];   // h chunk (BM x 128)

    const int tid  = threadIdx.x;
    const int wrp  = tid >> 5;      // 0..7  -> row group (2 rows each)
    const int lane = tid & 31;      // 0..31 -> col group (4 cols each)
    const int r0   = wrp * 2;
    const int c0   = lane * 4;
    const int mb   = blockIdx.x * BM;

    // Load y tile (BM x 128), coalesced float4
    for (int idx = tid; idx < BM * (D_ / 4); idx += 256) {
        int r  = idx >> 5;
        int c4 = (idx & 31) * 4;
        float4 v = *(const float4*)(y + (size_t)(mb + r) * D_ + c4);
        sy[r][c4]     = v.x;
        sy[r][c4 + 1] = v.y;
        sy[r][c4 + 2] = v.z;
        sy[r][c4 + 3] = v.w;
    }
    __syncthreads();

    float acc[2][4] = {};
    float dv[2]     = {0.f, 0.f};

    for (int ch = 0; ch < H_ / 128; ch++) {
        // ---- Phase A: z = y_tile @ W1[:, ch*128 : ch*128+128] ----
        float z[2][4] = {};
        const float* W1c = W1 + ch * 128 + c0;
        #pragma unroll 8
        for (int i = 0; i < D_; i++) {
            float4 wv = *(const float4*)(W1c + (size_t)i * H_);
            float a0 = sy[r0][i];
            float a1 = sy[r0 + 1][i];
            z[0][0] += a0 * wv.x; z[0][1] += a0 * wv.y; z[0][2] += a0 * wv.z; z[0][3] += a0 * wv.w;
            z[1][0] += a1 * wv.x; z[1][1] += a1 * wv.y; z[1][2] += a1 * wv.z; z[1][3] += a1 * wv.w;
        }

        const int kg = ch * 128 + c0;
        const float4 tb4 = *(const float4*)(g_tb + kg);
        const float4 cc4 = *(const float4*)(g_c + kg);
        #pragma unroll
        for (int rr = 0; rr < 2; rr++) {
            float h0 = tanhf(z[rr][0] + tb4.x);
            float h1 = tanhf(z[rr][1] + tb4.y);
            float h2 = tanhf(z[rr][2] + tb4.z);
            float h3 = tanhf(z[rr][3] + tb4.w);
            dv[rr] += cc4.x * (1.f - h0 * h0)
                    + cc4.y * (1.f - h1 * h1)
                    + cc4.z * (1.f - h2 * h2)
                    + cc4.w * (1.f - h3 * h3);
            float4 hv = make_float4(h0, h1, h2, h3);
            *(float4*)(&sh[r0 + rr][c0]) = hv;
        }
        __syncthreads();

        // ---- Phase B: acc += h_chunk @ W2[ch*128 : ch*128+128, :] ----
        const float* W2c = W2 + (size_t)ch * 128 * D_ + c0;
        #pragma unroll 8
        for (int kk = 0; kk < 128; kk++) {
            float4 wv = *(const float4*)(W2c + (size_t)kk * D_);
            float h0 = sh[r0][kk];
            float h1 = sh[r0 + 1][kk];
            acc[0][0] += h0 * wv.x; acc[0][1] += h0 * wv.y; acc[0][2] += h0 * wv.z; acc[0][3] += h0 * wv.w;
            acc[1][0] += h1 * wv.x; acc[1][1] += h1 * wv.y; acc[1][2] += h1 * wv.z; acc[1][3] += h1 * wv.w;
        }
        __syncthreads();
    }

    // ---- Epilogue: dy = acc + b2 ----
    const float4 b24 = *(const float4*)(b2 + c0);
    #pragma unroll
    for (int rr = 0; rr < 2; rr++) {
        float4 o;
        o.x = acc[rr][0] + b24.x;
        o.y = acc[rr][1] + b24.y;
        o.z = acc[rr][2] + b24.z;
        o.w = acc[rr][3] + b24.w;
        *(float4*)(out + (size_t)(mb + r0 + rr) * D_ + c0) = o;
    }

    // ---- Divergence: warp-reduce dv over the 32 col-groups ----
    #pragma unroll
    for (int rr = 0; rr < 2; rr++) {
        float v = dv[rr];
        #pragma unroll
        for (int off = 16; off > 0; off >>= 1)
            v += __shfl_xor_sync(0xFFFFFFFFu, v, off);
        if (lane == 0)
            out[(size_t)B_ * D_ + mb + r0 + rr] = -v;
    }
}

extern "C" void kernel_launch(void* const* d_in, const int* in_sizes, int n_in,
                              void* d_out, int out_size) {
    // Input order: t, y, logp, W1, b1, v1, W2, b2
    const float* t  = (const float*)d_in[0];
    const float* y  = (const float*)d_in[1];
    const float* W1 = (const float*)d_in[3];
    const float* b1 = (const float*)d_in[4];
    const float* v1 = (const float*)d_in[5];
    const float* W2 = (const float*)d_in[6];
    const float* b2 = (const float*)d_in[7];
    float* out = (float*)d_out;

    prep_kernel<<<1, H_>>>(t, W1, b1, v1, W2);
    ode_kernel<<<B_ / BM, 256>>>(y, W1, W2, b2, out);
}